// round 3
// baseline (speedup 1.0000x reference)
#include <cuda_runtime.h>
#include <cstdint>

#define BB   4
#define CC   64
#define NPTS 8192
#define OO   128
#define KNN  20
#define BN   (BB*NPTS)

// ---------------- scratch (static __device__ — no allocations) ----------------
__device__ float g_xt [BN*64];    // (b*N+n, c)   transposed points
__device__ float g_xx [BN];       // squared norms
__device__ int   g_idx[BN*KNN];   // global neighbor rows (b*N+m)
__device__ float g_Y  [BN*64];    // xt @ W1a^T   (only d<64 needed)
__device__ float g_V  [BN*64];    // xt @ (W1b-W1a)^T
__device__ float g_G  [BN*128];   // gated feature per point
__device__ float g_W1a[64*64];
__device__ float g_W1d[64*64];

// ---------------- helpers ----------------
#define FMA2(d,a,b,c) asm("fma.rn.f32x2 %0, %1, %2, %3;" : "=l"(d) : "l"(a), "l"(b), "l"(c))

__device__ __forceinline__ float2 upk(unsigned long long v) {
    float2 f;
    f.x = __uint_as_float((unsigned)(v & 0xffffffffULL));
    f.y = __uint_as_float((unsigned)(v >> 32));
    return f;
}

// ---------------- 0) weight prep: W1a = W1[:64,:64], W1d = W1[:64,64:] - W1a ----
__global__ void prep_w_kernel(const float* __restrict__ W1) {
    int i = blockIdx.x * 256 + threadIdx.x;
    if (i < 64*64) {
        int d = i >> 6, c = i & 63;
        float a = W1[d*128 + c];
        g_W1a[i] = a;
        g_W1d[i] = W1[d*128 + 64 + c] - a;
    }
}

// ---------------- 1) transpose x -> xt, squared norms ----------------
__global__ void __launch_bounds__(256) prep_x_kernel(const float* __restrict__ x) {
    int p = blockIdx.x * 256 + threadIdx.x;          // 0..BN-1
    int b = p >> 13, n = p & (NPTS-1);
    const float* xb = x + (size_t)b * CC * NPTS + n;
    float* dst = g_xt + (size_t)p * 64;
    float ss = 0.f;
#pragma unroll
    for (int c0 = 0; c0 < 64; c0 += 4) {
        float4 v;
        v.x = xb[(size_t)(c0+0)*NPTS];
        v.y = xb[(size_t)(c0+1)*NPTS];
        v.z = xb[(size_t)(c0+2)*NPTS];
        v.w = xb[(size_t)(c0+3)*NPTS];
        ss += v.x*v.x + v.y*v.y + v.z*v.z + v.w*v.w;
        *(float4*)(dst + c0) = v;
    }
    g_xx[p] = ss;
}

// ---------------- 2) brute-force KNN: rank by s = 2*dot - ||cand||^2 ----------
__global__ void __launch_bounds__(128) knn_kernel() {
    __shared__ __align__(16) float sc[128*64];       // candidate tile 32KB
    __shared__ float sxx[128];
    int tid = threadIdx.x;
    int b   = blockIdx.y;
    int base = b * NPTS;
    int q    = blockIdx.x * 128 + tid;               // query within batch

    // query vector, packed f32x2
    unsigned long long qp[32];
    {
        const ulonglong2* src = (const ulonglong2*)(g_xt + (size_t)(base + q) * 64);
#pragma unroll
        for (int i = 0; i < 16; i++) { ulonglong2 t = src[i]; qp[2*i] = t.x; qp[2*i+1] = t.y; }
    }

    float topv[KNN];
    int   topi[KNN];
#pragma unroll
    for (int i = 0; i < KNN; i++) { topv[i] = -3.4e38f; topi[i] = base; }
    float kth = -3.4e38f;

    for (int t = 0; t < NPTS/128; t++) {
        __syncthreads();
        {   // cooperative coalesced tile load
            const float4* gsrc = (const float4*)(g_xt + (size_t)(base + t*128) * 64);
            float4* sdst = (float4*)sc;
#pragma unroll
            for (int i = 0; i < 16; i++) sdst[tid + 128*i] = gsrc[tid + 128*i];
            sxx[tid] = g_xx[base + t*128 + tid];
        }
        __syncthreads();
#pragma unroll 2
        for (int j = 0; j < 128; j++) {
            const ulonglong2* cp = (const ulonglong2*)(sc + j*64);
            unsigned long long a0 = 0ULL, a1 = 0ULL, a2 = 0ULL, a3 = 0ULL;
#pragma unroll
            for (int i = 0; i < 8; i++) {
                ulonglong2 c01 = cp[2*i];
                ulonglong2 c23 = cp[2*i+1];
                FMA2(a0, qp[4*i+0], c01.x, a0);
                FMA2(a1, qp[4*i+1], c01.y, a1);
                FMA2(a2, qp[4*i+2], c23.x, a2);
                FMA2(a3, qp[4*i+3], c23.y, a3);
            }
            float2 f0 = upk(a0), f1 = upk(a2), f2 = upk(a1), f3 = upk(a3);
            float dot = (f0.x + f0.y) + (f1.x + f1.y) + ((f2.x + f2.y) + (f3.x + f3.y));
            float s = 2.f * dot - sxx[j];
            if (s > kth) {
                int ci = base + t*128 + j;
                int p = KNN - 1;
                while (p > 0 && topv[p-1] < s) {
                    topv[p] = topv[p-1]; topi[p] = topi[p-1]; --p;
                }
                topv[p] = s; topi[p] = ci;
                kth = topv[KNN-1];
            }
        }
    }
    int* dst = g_idx + (size_t)(base + q) * KNN;
#pragma unroll
    for (int i = 0; i < KNN; i++) dst[i] = topi[i];
}

// ---------------- 3/4/6) generic small GEMM: C[M,OUTD] = A[M,K] @ W[OUTD,ldW]^T --
template<int K, int OUTD, bool TOUT>
__global__ void __launch_bounds__(256) gemm_kernel(const float* __restrict__ A,
                                                   const float* __restrict__ W,
                                                   float* __restrict__ Cout, int ldW) {
    constexpr int KC = (K > 64) ? 64 : K;
    constexpr int NO = OUTD / 16;                    // outputs per thread
    __shared__ float As[16][K+1];
    __shared__ __align__(16) float Ws[KC][OUTD+4];
    int tid = threadIdx.x;
    int r = tid & 15, og = tid >> 4;
    int row0 = blockIdx.x * 16;

    for (int i = tid; i < 16*K; i += 256) As[i / K][i % K] = A[(size_t)row0 * K + i];

    float acc[NO];
#pragma unroll
    for (int j = 0; j < NO; j++) acc[j] = 0.f;

    for (int kb = 0; kb < K; kb += KC) {
        __syncthreads();                              // As ready / prev Ws drained
        for (int i = tid; i < OUTD*KC; i += 256) {
            int o = i / KC, c = i % KC;
            Ws[c][o] = W[o * ldW + kb + c];
        }
        __syncthreads();
#pragma unroll 8
        for (int c = 0; c < KC; c++) {
            float a = As[r][kb + c];
#pragma unroll
            for (int j4 = 0; j4 < NO; j4 += 4) {
                float4 wv = *(const float4*)&Ws[c][og*NO + j4];
                acc[j4+0] = fmaf(a, wv.x, acc[j4+0]);
                acc[j4+1] = fmaf(a, wv.y, acc[j4+1]);
                acc[j4+2] = fmaf(a, wv.z, acc[j4+2]);
                acc[j4+3] = fmaf(a, wv.w, acc[j4+3]);
            }
        }
    }
    int row = row0 + r;
    if (TOUT) {  // out[b][o][n]
        int b = row >> 13, n = row & (NPTS-1);
#pragma unroll
        for (int j = 0; j < NO; j++)
            Cout[((size_t)b*OUTD + og*NO + j) * NPTS + n] = acc[j];
    } else {
#pragma unroll
        for (int j = 0; j < NO; j++)
            Cout[(size_t)row*OUTD + og*NO + j] = acc[j];
    }
}

// ---------------- 5) gather + softmax over k + gated reduce -> G ----------------
__global__ void __launch_bounds__(256) gather_kernel() {
    int w = threadIdx.x >> 5, lane = threadIdx.x & 31;
    int p = blockIdx.x * 8 + w;
    __shared__ int s_nbr[8][KNN];
    if (lane < KNN) s_nbr[w][lane] = g_idx[(size_t)p*KNN + lane];
    __syncwarp();

    float2 v = *(const float2*)(g_V + (size_t)p*64 + lane*2);

    float hx[KNN], hy[KNN];
    float mx = -3.4e38f, my = -3.4e38f;
#pragma unroll
    for (int k = 0; k < KNN; k++) {
        int m = s_nbr[w][k];
        float2 y = *(const float2*)(g_Y + (size_t)m*64 + lane*2);
        hx[k] = y.x + v.x; hy[k] = y.y + v.y;
        mx = fmaxf(mx, hx[k]); my = fmaxf(my, hy[k]);
    }
    float sx = 0.f, sy = 0.f;
#pragma unroll
    for (int k = 0; k < KNN; k++) {
        hx[k] = __expf(hx[k] - mx); hy[k] = __expf(hy[k] - my);
        sx += hx[k]; sy += hy[k];
    }
    float rx = 1.f / sx, ry = 1.f / sy;
    float gx = 0.f, gy = 0.f;
#pragma unroll
    for (int k = 0; k < KNN; k++) {
        int m = s_nbr[w][k];
        float2 xn = *(const float2*)(g_xt + (size_t)m*64 + lane*2);
        gx = fmaf(xn.x, hx[k]*rx, gx);
        gy = fmaf(xn.y, hy[k]*ry, gy);
    }
    float2 ctr = *(const float2*)(g_xt + (size_t)p*64 + lane*2);
    float2 lo = make_float2(gx - ctr.x, gy - ctr.y);
    *(float2*)(g_G + (size_t)p*128 + lane*2)      = lo;   // g[c<64]
    *(float2*)(g_G + (size_t)p*128 + 64 + lane*2) = ctr;  // g[c>=64] = center exactly
}

// ---------------- launch ----------------
extern "C" void kernel_launch(void* const* d_in, const int* in_sizes, int n_in,
                              void* d_out, int out_size) {
    const float* x  = (const float*)d_in[0];
    const float* W1 = (const float*)d_in[1];
    const float* W2 = (const float*)d_in[2];
    float* out = (float*)d_out;

    float *xtp, *W1ap, *W1dp, *Yp, *Vp, *Gp;
    cudaGetSymbolAddress((void**)&xtp,  g_xt);
    cudaGetSymbolAddress((void**)&W1ap, g_W1a);
    cudaGetSymbolAddress((void**)&W1dp, g_W1d);
    cudaGetSymbolAddress((void**)&Yp,   g_Y);
    cudaGetSymbolAddress((void**)&Vp,   g_V);
    cudaGetSymbolAddress((void**)&Gp,   g_G);

    prep_w_kernel<<<16, 256>>>(W1);
    prep_x_kernel<<<BN/256, 256>>>(x);
    knn_kernel<<<dim3(NPTS/128, BB), 128>>>();
    gemm_kernel<64, 64, false><<<BN/16, 256>>>(xtp, W1ap, Yp, 64);
    gemm_kernel<64, 64, false><<<BN/16, 256>>>(xtp, W1dp, Vp, 64);
    gather_kernel<<<BN/8, 256>>>();
    gemm_kernel<128, 128, true><<<BN/16, 256>>>(Gp, W2, out, 128);
}

// round 6
// speedup vs baseline: 1.8361x; 1.8361x over previous
#include <cuda_runtime.h>
#include <cstdint>

#define BB   4
#define CC   64
#define NPTS 8192
#define KNN  20
#define BN   (BB*NPTS)
#define QT   128
#define CT   64

// ---------------- scratch (static __device__ — no allocations) ----------------
__device__ float g_xt [BN*64];     // (b*N+n, c)   transposed points
__device__ float g_xx [BN];        // squared norms
__device__ int   g_idx[BN*KNN];    // global neighbor rows (b*N+m)
__device__ float g_YV [BN*128];    // [0:64]=xt@W1a^T, [64:128]=xt@(W1b-W1a)^T
__device__ float g_G  [BN*128];    // gated feature per point
__device__ float g_W1cat[128*64];  // rows 0..63 = W1a, rows 64..127 = W1d

// ---------------- helpers ----------------
#define FMA2(d,a,b,c) asm("fma.rn.f32x2 %0, %1, %2, %3;" : "=l"(d) : "l"(a), "l"(b), "l"(c))

__device__ __forceinline__ float2 upk(unsigned long long v) {
    float2 f;
    f.x = __uint_as_float((unsigned)(v & 0xffffffffULL));
    f.y = __uint_as_float((unsigned)(v >> 32));
    return f;
}

// ---------------- 0) weight prep ----------------
__global__ void prep_w_kernel(const float* __restrict__ W1) {
    int i = blockIdx.x * 256 + threadIdx.x;
    if (i < 64*64) {
        int d = i >> 6, c = i & 63;
        float a = W1[d*128 + c];
        g_W1cat[d*64 + c]        = a;                      // Y weights (W1a)
        g_W1cat[(64+d)*64 + c]   = W1[d*128 + 64 + c] - a; // V weights (W1b - W1a)
    }
}

// ---------------- 1) transpose x -> xt, squared norms ----------------
__global__ void __launch_bounds__(256) prep_x_kernel(const float* __restrict__ x) {
    int p = blockIdx.x * 256 + threadIdx.x;          // 0..BN-1
    int b = p >> 13, n = p & (NPTS-1);
    const float* xb = x + (size_t)b * CC * NPTS + n;
    float* dst = g_xt + (size_t)p * 64;
    float ss = 0.f;
#pragma unroll
    for (int c0 = 0; c0 < 64; c0 += 4) {
        float4 v;
        v.x = xb[(size_t)(c0+0)*NPTS];
        v.y = xb[(size_t)(c0+1)*NPTS];
        v.z = xb[(size_t)(c0+2)*NPTS];
        v.w = xb[(size_t)(c0+3)*NPTS];
        ss += v.x*v.x + v.y*v.y + v.z*v.z + v.w*v.w;
        *(float4*)(dst + c0) = v;
    }
    g_xx[p] = ss;
}

// ---------------- 2) KNN: tiled distance GEMM + per-query top-k ----------------
// Block: QT=128 queries, 256 threads; candidates streamed in CT=64 tiles.
// Thread micro-tile: 8 queries x 4 candidates, k-pair-packed f32x2 accumulators.
// Rank by s = dot - 0.5*||cand||^2  (monotone equiv. of reference pd per query).
__global__ void __launch_bounds__(256, 2) knn_kernel() {
    extern __shared__ float sm[];
    float* qs  = sm;                   // [QT][64] plain rows
    float* cs  = qs + QT*64;           // [CT][64], 16B granules XOR-swizzled
    float* cxx = cs + CT*64;           // [CT]
    float* D   = cxx + CT;             // [QT][CT+1]

    int tid  = threadIdx.x;
    int b    = blockIdx.y;
    int base = b * NPTS;
    int q0   = blockIdx.x * QT;

    // load this block's queries (coalesced, plain layout)
    {
        const float4* src = (const float4*)(g_xt + (size_t)(base + q0) * 64);
        float4* dst = (float4*)qs;
#pragma unroll
        for (int i = 0; i < (QT*64/4)/256; i++)   // 8 per thread
            dst[tid + 256*i] = src[tid + 256*i];
    }

    const int tc = tid & 15, tq = tid >> 4;
    const int q8 = tq * 8, c4 = tc * 4;
    const unsigned key = (unsigned)(tc & 7);      // granule XOR key for b-frags

    float topv[KNN];
    int   topi[KNN];
#pragma unroll
    for (int i = 0; i < KNN; i++) { topv[i] = -3.4e38f; topi[i] = base; }
    float kth = -3.4e38f;

    for (int tile = 0; tile < NPTS/CT; tile++) {
        // ---- load candidate tile, swizzled granules (conflict-free STS128) ----
        {
            const float4* src = (const float4*)(g_xt + (size_t)(base + tile*CT) * 64);
#pragma unroll
            for (int u = 0; u < (CT*64/4)/256; u++) {   // 4 per thread
                int i = tid + 256*u;                     // 0..1023
                int c = i >> 4, gk = i & 15;
                float4 v = src[i];
                *(float4*)(cs + c*64 + (((unsigned)gk ^ ((unsigned)(c>>2) & 7u)) << 2)) = v;
            }
            if (tid < CT) cxx[tid] = g_xx[base + tile*CT + tid];
        }
        __syncthreads();   // tile ready (also: previous scan finished before D overwrite)

        // ---- distance GEMM: acc[q][c] over k-pairs ----
        unsigned long long acc[8][4];
#pragma unroll
        for (int i = 0; i < 8; i++)
#pragma unroll
            for (int j = 0; j < 4; j++) acc[i][j] = 0ULL;

#pragma unroll 4
        for (int g = 0; g < 16; g++) {             // granule = 4 consecutive k
            unsigned sg = ((unsigned)g ^ key) << 2;
            ulonglong2 b0 = *(const ulonglong2*)(cs + (c4+0)*64 + sg);
            ulonglong2 b1 = *(const ulonglong2*)(cs + (c4+1)*64 + sg);
            ulonglong2 b2 = *(const ulonglong2*)(cs + (c4+2)*64 + sg);
            ulonglong2 b3 = *(const ulonglong2*)(cs + (c4+3)*64 + sg);
#pragma unroll
            for (int i = 0; i < 8; i++) {
                ulonglong2 a = *(const ulonglong2*)(qs + (q8+i)*64 + (g << 2));
                FMA2(acc[i][0], a.x, b0.x, acc[i][0]);
                FMA2(acc[i][0], a.y, b0.y, acc[i][0]);
                FMA2(acc[i][1], a.x, b1.x, acc[i][1]);
                FMA2(acc[i][1], a.y, b1.y, acc[i][1]);
                FMA2(acc[i][2], a.x, b2.x, acc[i][2]);
                FMA2(acc[i][2], a.y, b2.y, acc[i][2]);
                FMA2(acc[i][3], a.x, b3.x, acc[i][3]);
                FMA2(acc[i][3], a.y, b3.y, acc[i][3]);
            }
        }

        // ---- horizontal add, fold -0.5*||c||^2, write scores ----
        {
            float4 cx = *(const float4*)(cxx + c4);
#pragma unroll
            for (int i = 0; i < 8; i++) {
                float* drow = D + (size_t)(q8+i)*(CT+1) + c4;
                float2 p0 = upk(acc[i][0]);
                float2 p1 = upk(acc[i][1]);
                float2 p2 = upk(acc[i][2]);
                float2 p3 = upk(acc[i][3]);
                drow[0] = p0.x + p0.y - 0.5f*cx.x;
                drow[1] = p1.x + p1.y - 0.5f*cx.y;
                drow[2] = p2.x + p2.y - 0.5f*cx.z;
                drow[3] = p3.x + p3.y - 0.5f*cx.w;
            }
        }
        __syncthreads();   // D ready

        // ---- per-query top-k scan (threads 0..127, conflict-free stride-65) ----
        if (tid < QT) {
            const float* drow = D + (size_t)tid * (CT+1);
            int gbase = base + tile*CT;
#pragma unroll 4
            for (int j = 0; j < CT; j++) {
                float s = drow[j];
                if (s > kth) {
                    int p = KNN - 1;
                    while (p > 0 && topv[p-1] < s) {
                        topv[p] = topv[p-1]; topi[p] = topi[p-1]; --p;
                    }
                    topv[p] = s; topi[p] = gbase + j;
                    kth = topv[KNN-1];
                }
            }
        }
        // no trailing sync needed: next tile's load only touches cs/cxx (disjoint
        // from D), and the next sync precedes the next D overwrite.
    }

    if (tid < QT) {
        int* dst = g_idx + (size_t)(base + q0 + tid) * KNN;
#pragma unroll
        for (int i = 0; i < KNN; i++) dst[i] = topi[i];
    }
}

// ---------------- 3/5) generic small GEMM: C[M,OUTD] = A[M,K] @ W[OUTD,ldW]^T --
template<int K, int OUTD, bool TOUT>
__global__ void __launch_bounds__(256) gemm_kernel(const float* __restrict__ A,
                                                   const float* __restrict__ W,
                                                   float* __restrict__ Cout, int ldW) {
    constexpr int KC = (K > 64) ? 64 : K;
    constexpr int NO = OUTD / 16;                    // outputs per thread
    __shared__ float As[16][K+1];
    __shared__ __align__(16) float Ws[KC][OUTD+4];
    int tid = threadIdx.x;
    int r = tid & 15, og = tid >> 4;
    int row0 = blockIdx.x * 16;

    for (int i = tid; i < 16*K; i += 256) As[i / K][i % K] = A[(size_t)row0 * K + i];

    float acc[NO];
#pragma unroll
    for (int j = 0; j < NO; j++) acc[j] = 0.f;

    for (int kb = 0; kb < K; kb += KC) {
        __syncthreads();                              // As ready / prev Ws drained
        for (int i = tid; i < OUTD*KC; i += 256) {
            int o = i / KC, c = i % KC;
            Ws[c][o] = W[o * ldW + kb + c];
        }
        __syncthreads();
#pragma unroll 8
        for (int c = 0; c < KC; c++) {
            float a = As[r][kb + c];
#pragma unroll
            for (int j4 = 0; j4 < NO; j4 += 4) {
                float4 wv = *(const float4*)&Ws[c][og*NO + j4];
                acc[j4+0] = fmaf(a, wv.x, acc[j4+0]);
                acc[j4+1] = fmaf(a, wv.y, acc[j4+1]);
                acc[j4+2] = fmaf(a, wv.z, acc[j4+2]);
                acc[j4+3] = fmaf(a, wv.w, acc[j4+3]);
            }
        }
    }
    int row = row0 + r;
    if (TOUT) {  // out[b][o][n]
        int b = row >> 13, n = row & (NPTS-1);
#pragma unroll
        for (int j = 0; j < NO; j++)
            Cout[((size_t)b*OUTD + og*NO + j) * NPTS + n] = acc[j];
    } else {
#pragma unroll
        for (int j = 0; j < NO; j++)
            Cout[(size_t)row*OUTD + og*NO + j] = acc[j];
    }
}

// ---------------- 4) gather + softmax over k + gated reduce -> G ----------------
__global__ void __launch_bounds__(256) gather_kernel() {
    int w = threadIdx.x >> 5, lane = threadIdx.x & 31;
    int p = blockIdx.x * 8 + w;
    __shared__ int s_nbr[8][KNN];
    if (lane < KNN) s_nbr[w][lane] = g_idx[(size_t)p*KNN + lane];
    __syncwarp();

    float2 v = *(const float2*)(g_YV + (size_t)p*128 + 64 + lane*2);   // V part (center)

    float hx[KNN], hy[KNN];
    float mx = -3.4e38f, my = -3.4e38f;
#pragma unroll
    for (int k = 0; k < KNN; k++) {
        int m = s_nbr[w][k];
        float2 y = *(const float2*)(g_YV + (size_t)m*128 + lane*2);    // Y part (neighbor)
        hx[k] = y.x + v.x; hy[k] = y.y + v.y;
        mx = fmaxf(mx, hx[k]); my = fmaxf(my, hy[k]);
    }
    float sx = 0.f, sy = 0.f;
#pragma unroll
    for (int k = 0; k < KNN; k++) {
        hx[k] = __expf(hx[k] - mx); hy[k] = __expf(hy[k] - my);
        sx += hx[k]; sy += hy[k];
    }
    float rx = 1.f / sx, ry = 1.f / sy;
    float gx = 0.f, gy = 0.f;
#pragma unroll
    for (int k = 0; k < KNN; k++) {
        int m = s_nbr[w][k];
        float2 xn = *(const float2*)(g_xt + (size_t)m*64 + lane*2);
        gx = fmaf(xn.x, hx[k]*rx, gx);
        gy = fmaf(xn.y, hy[k]*ry, gy);
    }
    float2 ctr = *(const float2*)(g_xt + (size_t)p*64 + lane*2);
    float2 lo = make_float2(gx - ctr.x, gy - ctr.y);
    *(float2*)(g_G + (size_t)p*128 + lane*2)      = lo;   // g[c<64]
    *(float2*)(g_G + (size_t)p*128 + 64 + lane*2) = ctr;  // g[c>=64] = center exactly
}

// ---------------- launch ----------------
extern "C" void kernel_launch(void* const* d_in, const int* in_sizes, int n_in,
                              void* d_out, int out_size) {
    const float* x  = (const float*)d_in[0];
    const float* W1 = (const float*)d_in[1];
    const float* W2 = (const float*)d_in[2];
    float* out = (float*)d_out;

    float *xtp, *W1catp, *YVp, *Gp;
    cudaGetSymbolAddress((void**)&xtp,    g_xt);
    cudaGetSymbolAddress((void**)&W1catp, g_W1cat);
    cudaGetSymbolAddress((void**)&YVp,    g_YV);
    cudaGetSymbolAddress((void**)&Gp,     g_G);

    prep_w_kernel<<<16, 256>>>(W1);
    prep_x_kernel<<<BN/256, 256>>>(x);

    size_t shm = (size_t)(QT*64 + CT*64 + CT + QT*(CT+1)) * sizeof(float);  // 82688 B
    cudaFuncSetAttribute(knn_kernel, cudaFuncAttributeMaxDynamicSharedMemorySize, (int)shm);
    knn_kernel<<<dim3(NPTS/QT, BB), 256, shm>>>();

    gemm_kernel<64, 128, false><<<BN/16, 256>>>(xtp, W1catp, YVp, 64);
    gather_kernel<<<BN/8, 256>>>();
    gemm_kernel<128, 128, true><<<BN/16, 256>>>(Gp, W2, out, 128);
}